// round 3
// baseline (speedup 1.0000x reference)
#include <cuda_runtime.h>
#include <cstdint>

// Problem constants
#define Bb    2
#define Ll    32768            // T*H*W = 8*64*64
#define Cc    128
#define NTOK  512              // tokens per window (2*64*4)
#define NHEADS 4
#define HDIM  32
// window decomposition: w = b*64 + tB*16 + wB ; n = t*256 + h*4 + ws
// l(global) = (tB*2 + t)*4096 + h*64 + wB*4 + ws

static __device__ __forceinline__ float ex2f(float x){
    float y; asm("ex2.approx.ftz.f32 %0, %1;" : "=f"(y) : "f"(x)); return y;
}
static __device__ __forceinline__ unsigned long long fma2(unsigned long long a, unsigned long long b, unsigned long long c){
    unsigned long long d; asm("fma.rn.f32x2 %0, %1, %2, %3;" : "=l"(d) : "l"(a), "l"(b), "l"(c)); return d;
}
static __device__ __forceinline__ unsigned long long add2(unsigned long long a, unsigned long long b){
    unsigned long long d; asm("add.rn.f32x2 %0, %1, %2;" : "=l"(d) : "l"(a), "l"(b)); return d;
}
static __device__ __forceinline__ unsigned long long mul2(unsigned long long a, unsigned long long b){
    unsigned long long d; asm("mul.rn.f32x2 %0, %1, %2;" : "=l"(d) : "l"(a), "l"(b)); return d;
}
static __device__ __forceinline__ unsigned long long pack2(float x, float y){
    unsigned long long d; asm("mov.b64 %0, {%1, %2};" : "=l"(d) : "f"(x), "f"(y)); return d;
}
static __device__ __forceinline__ float2 unpack2(unsigned long long a){
    float2 r; asm("mov.b64 {%0, %1}, %2;" : "=f"(r.x), "=f"(r.y) : "l"(a)); return r;
}
static __device__ __forceinline__ uint32_t s2u(const void* p){
    uint32_t a;
    asm("{ .reg .u64 t; cvta.to.shared.u64 t, %1; cvt.u32.u64 %0, t; }" : "=r"(a) : "l"(p));
    return a;
}
static __device__ __forceinline__ void lds2u64(uint32_t a, unsigned long long& x, unsigned long long& y){
    asm volatile("ld.shared.v2.u64 {%0, %1}, [%2];" : "=l"(x), "=l"(y) : "r"(a));
}

// smem layout (floats):
//   Ks : 512*32            (K rows, 128B stride; broadcast reads only)
//   Vs : 512*36            (V rows padded to 144B so epilogue strided LDS.128 is conflict-free)
//   Ws : 27*32             ([tap][d] depthwise weights for this head)
//   Bs : 32                (bias)
#define SMEM_FLOATS (NTOK*32 + NTOK*36 + 27*32 + 32)   // 35712 floats = 142848 B

#define CHUNK 8

__global__ void __launch_bounds__(256, 1)
lepe_attn_kernel(const float* __restrict__ qkv,
                 const float* __restrict__ lw,
                 const float* __restrict__ lb,
                 float* __restrict__ out)
{
    extern __shared__ float sm[];
    float* Ks  = sm;
    float* Vs  = sm + NTOK*32;
    float* Wsm = Vs + NTOK*36;
    float* Bsm = Wsm + 27*32;

    const int bx   = blockIdx.x;          // 0..511 : (window, head)
    const int w    = bx >> 2;             // window 0..127
    const int head = bx & 3;
    const int b  = w >> 6;
    const int tB = (w >> 4) & 3;
    const int wB = w & 15;
    const int tid = threadIdx.x;

    const size_t batch_off = (size_t)b * Ll * Cc;
    const int chan  = head * HDIM;
    const int lbase = tB*2*4096 + wB*4;

    const float* kglob = qkv + (size_t)1 * Bb * Ll * Cc + batch_off;
    const float* vglob = qkv + (size_t)2 * Bb * Ll * Cc + batch_off;

    // ---- stage K, V into smem (coalesced: 4 rows x 128B per warp) ----
    {
        const int vec = tid & 7;
        for (int r = (tid >> 3); r < NTOK; r += 32){
            const int t = r >> 8, h = (r >> 2) & 63, ws = r & 3;
            const size_t l = (size_t)(lbase + t*4096 + h*64 + ws);
            float4 kk = ((const float4*)(kglob + l*Cc + chan))[vec];
            float4 vv = ((const float4*)(vglob + l*Cc + chan))[vec];
            ((float4*)(Ks + r*32))[vec] = kk;
            *((float4*)(Vs + r*36 + vec*4)) = vv;
        }
        for (int idx = tid; idx < 27*32; idx += 256){
            const int tap = idx >> 5, d = idx & 31;
            Wsm[tap*32 + d] = lw[(chan + d)*27 + tap];
        }
        if (tid < 32) Bsm[tid] = lb[chan + tid];
    }

    // ---- this thread's TWO query rows (pre-scaled into log2 domain) ----
    const int rowA = tid;          // 0..255
    const int rowB = tid + 256;    // 256..511
    const int rtA = rowA >> 8, rhA = (rowA >> 2) & 63, rwsA = rowA & 3;
    const int rtB = rowB >> 8, rhB = (rowB >> 2) & 63, rwsB = rowB & 3;
    const size_t lrowA = (size_t)(lbase + rtA*4096 + rhA*64 + rwsA);
    const size_t lrowB = (size_t)(lbase + rtB*4096 + rhB*64 + rwsB);

    unsigned long long qa[16], qb[16];
    {
        const float sc = 0.17677669529663689f * 1.4426950408889634f; // scale * log2(e)
        const float4* qgA = (const float4*)(qkv + batch_off + lrowA*Cc + chan);
        const float4* qgB = (const float4*)(qkv + batch_off + lrowB*Cc + chan);
        #pragma unroll
        for (int v = 0; v < 8; v++){
            float4 q1 = qgA[v];
            qa[2*v]   = pack2(q1.x*sc, q1.y*sc);
            qa[2*v+1] = pack2(q1.z*sc, q1.w*sc);
            float4 q2v = qgB[v];
            qb[2*v]   = pack2(q2v.x*sc, q2v.y*sc);
            qb[2*v+1] = pack2(q2v.z*sc, q2v.w*sc);
        }
    }
    __syncthreads();

    const uint32_t KsA = s2u(Ks);
    const uint32_t VsA = s2u(Vs);

    unsigned long long oa[16], ob[16];
    #pragma unroll
    for (int t = 0; t < 16; t++){ oa[t] = 0ull; ob[t] = 0ull; }
    float mA = -1e30f, lsA = 0.f;
    float mB = -1e30f, lsB = 0.f;

    // ---- flash mainloop: chunks of CHUNK keys; K/V loaded once, used for both rows ----
    for (int j0 = 0; j0 < NTOK; j0 += CHUNK){
        float sa[CHUNK], sb[CHUNK];
        #pragma unroll
        for (int jj = 0; jj < CHUNK; jj++){
            const uint32_t ka = KsA + (uint32_t)(j0 + jj)*128;
            unsigned long long a0=0ull,a1=0ull,a2=0ull,a3=0ull;
            unsigned long long b0=0ull,b1=0ull,b2=0ull,b3=0ull;
            unsigned long long k0, k1, k2, k3;
            #pragma unroll
            for (int v = 0; v < 8; v += 2){
                lds2u64(ka + v*16, k0, k1);
                a0 = fma2(qa[2*v],   k0, a0);
                a1 = fma2(qa[2*v+1], k1, a1);
                b0 = fma2(qb[2*v],   k0, b0);
                b1 = fma2(qb[2*v+1], k1, b1);
                lds2u64(ka + (v+1)*16, k2, k3);
                a2 = fma2(qa[2*v+2], k2, a2);
                a3 = fma2(qa[2*v+3], k3, a3);
                b2 = fma2(qb[2*v+2], k2, b2);
                b3 = fma2(qb[2*v+3], k3, b3);
            }
            a0 = add2(a0, a1); a2 = add2(a2, a3); a0 = add2(a0, a2);
            b0 = add2(b0, b1); b2 = add2(b2, b3); b0 = add2(b0, b2);
            float2 fa = unpack2(a0);
            float2 fb = unpack2(b0);
            sa[jj] = fa.x + fa.y;
            sb[jj] = fb.x + fb.y;
        }
        // online softmax update (row A)
        float cmA = sa[0], cmB = sb[0];
        #pragma unroll
        for (int jj = 1; jj < CHUNK; jj++){ cmA = fmaxf(cmA, sa[jj]); cmB = fmaxf(cmB, sb[jj]); }
        const float nmA = fmaxf(mA, cmA);
        const float nmB = fmaxf(mB, cmB);
        const float corrA = ex2f(mA - nmA);
        const float corrB = ex2f(mB - nmB);
        mA = nmA; mB = nmB;
        float psA = 0.f, psB = 0.f;
        #pragma unroll
        for (int jj = 0; jj < CHUNK; jj++){
            sa[jj] = ex2f(sa[jj] - nmA); psA += sa[jj];
            sb[jj] = ex2f(sb[jj] - nmB); psB += sb[jj];
        }
        lsA = lsA*corrA + psA;
        lsB = lsB*corrB + psB;
        const unsigned long long cA2 = pack2(corrA, corrA);
        const unsigned long long cB2 = pack2(corrB, corrB);
        #pragma unroll
        for (int t = 0; t < 16; t++){ oa[t] = mul2(oa[t], cA2); ob[t] = mul2(ob[t], cB2); }
        // PV accumulate: V row loaded once, used for both query rows
        #pragma unroll
        for (int jj = 0; jj < CHUNK; jj++){
            const uint32_t va = VsA + (uint32_t)(j0 + jj)*144;
            const unsigned long long pa2 = pack2(sa[jj], sa[jj]);
            const unsigned long long pb2 = pack2(sb[jj], sb[jj]);
            unsigned long long v0, v1;
            #pragma unroll
            for (int v = 0; v < 8; v++){
                lds2u64(va + v*16, v0, v1);
                oa[2*v]   = fma2(pa2, v0, oa[2*v]);
                oa[2*v+1] = fma2(pa2, v1, oa[2*v+1]);
                ob[2*v]   = fma2(pb2, v0, ob[2*v]);
                ob[2*v+1] = fma2(pb2, v1, ob[2*v+1]);
            }
        }
    }

    // normalize
    {
        const float invA = 1.f / lsA;
        const float invB = 1.f / lsB;
        const unsigned long long iA2 = pack2(invA, invA);
        const unsigned long long iB2 = pack2(invB, invB);
        #pragma unroll
        for (int t = 0; t < 16; t++){ oa[t] = mul2(oa[t], iA2); ob[t] = mul2(ob[t], iB2); }
    }

    // ---- fused LePE + bias + store, per query row ----
    const uint32_t WsA = s2u(Wsm);
    #pragma unroll
    for (int r = 0; r < 2; r++){
        unsigned long long* o2 = r ? ob : oa;
        const int rt  = r ? rtB  : rtA;
        const int rh  = r ? rhB  : rhA;
        const int rws = r ? rwsB : rwsA;
        const size_t lrow = r ? lrowB : lrowA;

        #pragma unroll
        for (int dt = -1; dt <= 1; dt++){
            const int tt = rt + dt;
            if ((unsigned)tt >= 2u) continue;
            #pragma unroll
            for (int dh = -1; dh <= 1; dh++){
                const int hh = rh + dh;
                if ((unsigned)hh >= 64u) continue;
                #pragma unroll
                for (int dw = -1; dw <= 1; dw++){
                    const int ww2 = rws + dw;
                    if ((unsigned)ww2 >= 4u) continue;
                    const int n2  = tt*256 + hh*4 + ww2;
                    const int tap = (dt+1)*9 + (dh+1)*3 + (dw+1);
                    const uint32_t va = VsA + (uint32_t)n2*144;
                    const uint32_t wa = WsA + (uint32_t)tap*128;
                    #pragma unroll
                    for (int v = 0; v < 8; v++){
                        unsigned long long v0, v1, w0, w1;
                        lds2u64(va + v*16, v0, v1);
                        lds2u64(wa + v*16, w0, w1);
                        o2[2*v]   = fma2(v0, w0, o2[2*v]);
                        o2[2*v+1] = fma2(v1, w1, o2[2*v+1]);
                    }
                }
            }
        }

        float* op = out + batch_off + lrow*Cc + chan;
        #pragma unroll
        for (int v = 0; v < 8; v++){
            float2 x  = unpack2(o2[2*v]);
            float2 y  = unpack2(o2[2*v+1]);
            float4 r4;
            r4.x = x.x + Bsm[4*v + 0];
            r4.y = x.y + Bsm[4*v + 1];
            r4.z = y.x + Bsm[4*v + 2];
            r4.w = y.y + Bsm[4*v + 3];
            ((float4*)op)[v] = r4;
        }
    }
}

extern "C" void kernel_launch(void* const* d_in, const int* in_sizes, int n_in,
                              void* d_out, int out_size)
{
    const float* qkv = (const float*)d_in[0];
    const float* lw  = (const float*)d_in[1];
    const float* lb  = (const float*)d_in[2];
    float* out       = (float*)d_out;

    const int smem_bytes = SMEM_FLOATS * 4;   // 142848
    cudaFuncSetAttribute(lepe_attn_kernel, cudaFuncAttributeMaxDynamicSharedMemorySize, smem_bytes);
    lepe_attn_kernel<<<512, 256, smem_bytes>>>(qkv, lw, lb, out);
}

// round 5
// speedup vs baseline: 2.3556x; 2.3556x over previous
#include <cuda_runtime.h>
#include <cuda_bf16.h>
#include <cstdint>

#define Bb 2
#define Ll 32768
#define Cc 128
#define NTOK 512
#define HD 32

// ---- smem byte offsets ----
#define KH_OFF  0           // K hi: 512 rows x 64B (swizzled)     32768
#define KL_OFF  32768       // K lo                                32768
#define VTH_OFF 65536       // V^T hi: 32 d-rows x 1024B (swz)     32768
#define VTL_OFF 98304       // V^T lo                              32768
#define VF_OFF  131072      // V fp32 [512][36]                    73728
#define WS_OFF  204800      // weights [27][32] f32                 3456
#define BS_OFF  208256      // bias [32] f32                         128
#define SMEM_BYTES 208384
#define OS_OFF  0           // O fp32 [512][36] overlays K/VT after mainloop

static __device__ __forceinline__ float ex2f(float x){
    float y; asm("ex2.approx.ftz.f32 %0, %1;" : "=f"(y) : "f"(x)); return y;
}
static __device__ __forceinline__ uint32_t s2u(const void* p){
    uint32_t a;
    asm("{ .reg .u64 t; cvta.to.shared.u64 t, %1; cvt.u32.u64 %0, t; }" : "=r"(a) : "l"(p));
    return a;
}
// pack two f32 -> bf16x2 (a -> low half, b -> high half)
static __device__ __forceinline__ uint32_t pk2(float a, float b){
    uint32_t r; asm("cvt.rn.bf16x2.f32 %0, %1, %2;" : "=r"(r) : "f"(b), "f"(a)); return r;
}
// hi/lo split of a pair
static __device__ __forceinline__ void hilo2(float x, float y, uint32_t& h, uint32_t& l){
    h = pk2(x, y);
    float fx = __uint_as_float(h << 16);
    float fy = __uint_as_float(h & 0xffff0000u);
    l = pk2(x - fx, y - fy);
}
static __device__ __forceinline__ void ldm4(uint32_t* r, uint32_t a){
    asm volatile("ldmatrix.sync.aligned.m8n8.x4.shared.b16 {%0,%1,%2,%3}, [%4];"
        : "=r"(r[0]), "=r"(r[1]), "=r"(r[2]), "=r"(r[3]) : "r"(a));
}
static __device__ __forceinline__ void mma16816(float* d, const uint32_t* a, uint32_t b0, uint32_t b1){
    asm volatile("mma.sync.aligned.m16n8k16.row.col.f32.bf16.bf16.f32 "
        "{%0,%1,%2,%3},{%4,%5,%6,%7},{%8,%9},{%0,%1,%2,%3};"
        : "+f"(d[0]), "+f"(d[1]), "+f"(d[2]), "+f"(d[3])
        : "r"(a[0]), "r"(a[1]), "r"(a[2]), "r"(a[3]), "r"(b0), "r"(b1));
}
static __device__ __forceinline__ void sts_u16(uint32_t a, uint32_t v){
    asm volatile("st.shared.u16 [%0], %1;" :: "r"(a), "h"((unsigned short)v) : "memory");
}
static __device__ __forceinline__ void sts_v4(uint32_t a, uint32_t x, uint32_t y, uint32_t z, uint32_t w){
    asm volatile("st.shared.v4.b32 [%0], {%1,%2,%3,%4};" :: "r"(a), "r"(x), "r"(y), "r"(z), "r"(w) : "memory");
}
// K row addressing: 64B rows; 16B-chunk c rotated by (row>>1) so ldmatrix (8 rows, fixed c) is conflict-free
static __device__ __forceinline__ uint32_t kaddr(int n, int c){
    return (uint32_t)n*64u + ((((uint32_t)c + ((uint32_t)n >> 1)) & 3u) * 16u);
}
// V^T addressing: 1024B d-rows; low 3 bits of key-chunk XOR d
static __device__ __forceinline__ uint32_t vtaddr(int d, int kc){
    uint32_t sw = ((uint32_t)kc & ~7u) | (((uint32_t)(kc ^ d)) & 7u);
    return (uint32_t)d*1024u + sw*16u;
}

__global__ void __launch_bounds__(256, 1)
lepe_hmma(const float* __restrict__ qkv,
          const float* __restrict__ lw,
          const float* __restrict__ lb,
          float* __restrict__ out)
{
    extern __shared__ char sm[];
    const uint32_t smb = s2u(sm);
    const int tid = threadIdx.x;
    const int wid = tid >> 5, lane = tid & 31;

    const int bx = blockIdx.x;            // (window, head)
    const int win = bx >> 2, head = bx & 3;
    const int b  = win >> 6;
    const int tB = (win >> 4) & 3;
    const int wB = win & 15;
    const size_t batch_off = (size_t)b * Ll * Cc;
    const int chan  = head * HD;
    const int lbase = tB*8192 + wB*4;

    const float* qg = qkv + batch_off;
    const float* kg = qkv + (size_t)1*Bb*Ll*Cc + batch_off;
    const float* vg = qkv + (size_t)2*Bb*Ll*Cc + batch_off;

    // ---------- stage K (hi/lo), V^T (hi/lo), V fp32 ----------
    {
        const int q = tid & 3;            // 4 threads per row, 8 d-values each
        const int rbase = tid >> 2;       // 0..63
        for (int it = 0; it < 8; it++){
            const int j = it*64 + rbase;
            const int t = j >> 8, h = (j >> 2) & 63, ws = j & 3;
            const size_t l = (size_t)(lbase + t*4096 + h*64 + ws);
            const float4 k0 = *(const float4*)(kg + l*Cc + chan + q*8);
            const float4 k1 = *(const float4*)(kg + l*Cc + chan + q*8 + 4);
            uint32_t hh[4], ll[4];
            hilo2(k0.x, k0.y, hh[0], ll[0]);
            hilo2(k0.z, k0.w, hh[1], ll[1]);
            hilo2(k1.x, k1.y, hh[2], ll[2]);
            hilo2(k1.z, k1.w, hh[3], ll[3]);
            const uint32_t ka = kaddr(j, q);
            sts_v4(smb + KH_OFF + ka, hh[0], hh[1], hh[2], hh[3]);
            sts_v4(smb + KL_OFF + ka, ll[0], ll[1], ll[2], ll[3]);

            const float4 v0 = *(const float4*)(vg + l*Cc + chan + q*8);
            const float4 v1 = *(const float4*)(vg + l*Cc + chan + q*8 + 4);
            *(float4*)(sm + VF_OFF + j*144 + q*32)      = v0;
            *(float4*)(sm + VF_OFF + j*144 + q*32 + 16) = v1;
            hilo2(v0.x, v0.y, hh[0], ll[0]);
            hilo2(v0.z, v0.w, hh[1], ll[1]);
            hilo2(v1.x, v1.y, hh[2], ll[2]);
            hilo2(v1.z, v1.w, hh[3], ll[3]);
            const int kc = j >> 3;
            const uint32_t ko = (uint32_t)(j & 7) * 2u;
            #pragma unroll
            for (int e = 0; e < 8; e++){
                const int d = q*8 + e;
                const uint32_t hb = (e & 1) ? (hh[e>>1] >> 16) : (hh[e>>1] & 0xffffu);
                const uint32_t lbv = (e & 1) ? (ll[e>>1] >> 16) : (ll[e>>1] & 0xffffu);
                const uint32_t va = vtaddr(d, kc) + ko;
                sts_u16(smb + VTH_OFF + va, hb);
                sts_u16(smb + VTL_OFF + va, lbv);
            }
        }
        for (int idx = tid; idx < 27*32; idx += 256){
            const int tap = idx >> 5, d = idx & 31;
            ((float*)(sm + WS_OFF))[tap*32 + d] = lw[(chan + d)*27 + tap];
        }
        if (tid < 32) ((float*)(sm + BS_OFF))[tid] = lb[chan + tid];
    }

    // ---------- Q fragments from gmem (scaled into log2 domain, hi/lo) ----------
    const int qb = wid * 64;
    uint32_t qh[4][2][4], ql[4][2][4];
    {
        const float sc = 0.17677669529663689f * 1.4426950408889634f;
        #pragma unroll
        for (int mt = 0; mt < 4; mt++){
            const int r0 = qb + mt*16 + (lane >> 2);
            const int r1 = r0 + 8;
            const int t0 = r0 >> 8, h0 = (r0 >> 2) & 63, w0 = r0 & 3;
            const int t1 = r1 >> 8, h1 = (r1 >> 2) & 63, w1 = r1 & 3;
            const float* p0 = qg + (size_t)(lbase + t0*4096 + h0*64 + w0)*Cc + chan;
            const float* p1 = qg + (size_t)(lbase + t1*4096 + h1*64 + w1)*Cc + chan;
            #pragma unroll
            for (int kt = 0; kt < 2; kt++){
                const int d0 = kt*16 + 2*(lane & 3);
                const float2 x0 = *(const float2*)(p0 + d0);
                const float2 x1 = *(const float2*)(p1 + d0);
                const float2 x2 = *(const float2*)(p0 + d0 + 8);
                const float2 x3 = *(const float2*)(p1 + d0 + 8);
                hilo2(x0.x*sc, x0.y*sc, qh[mt][kt][0], ql[mt][kt][0]);
                hilo2(x1.x*sc, x1.y*sc, qh[mt][kt][1], ql[mt][kt][1]);
                hilo2(x2.x*sc, x2.y*sc, qh[mt][kt][2], ql[mt][kt][2]);
                hilo2(x3.x*sc, x3.y*sc, qh[mt][kt][3], ql[mt][kt][3]);
            }
        }
    }
    __syncthreads();

    // ---------- mainloop: 32 subchunks of 16 keys ----------
    float oAcc[4][4][4];
    #pragma unroll
    for (int a = 0; a < 4; a++)
        #pragma unroll
        for (int b2 = 0; b2 < 4; b2++)
            #pragma unroll
            for (int c = 0; c < 4; c++) oAcc[a][b2][c] = 0.f;
    float ps[4][2] = {{0.f,0.f},{0.f,0.f},{0.f,0.f},{0.f,0.f}};

    const int lg = lane >> 3, lr = lane & 7;
    #pragma unroll 1
    for (int cs = 0; cs < 32; cs++){
        const int j0 = cs * 16;
        // K fragments (B operand for QK): tiles [8 keys x 8 d]
        uint32_t kh[2][4], kl2[2][4];
        #pragma unroll
        for (int nt = 0; nt < 2; nt++){
            const uint32_t a = smb + KH_OFF + kaddr(j0 + nt*8 + lr, lg);
            ldm4(kh[nt], a);
            ldm4(kl2[nt], a + (KL_OFF - KH_OFF));
        }
        // S = Q K^T (3 split terms)
        float s[4][2][4];
        #pragma unroll
        for (int mt = 0; mt < 4; mt++)
            #pragma unroll
            for (int nt = 0; nt < 2; nt++){
                float* sd = s[mt][nt];
                sd[0]=sd[1]=sd[2]=sd[3]=0.f;
                mma16816(sd, qh[mt][0], kh[nt][0], kh[nt][1]);
                mma16816(sd, qh[mt][1], kh[nt][2], kh[nt][3]);
                mma16816(sd, ql[mt][0], kh[nt][0], kh[nt][1]);
                mma16816(sd, ql[mt][1], kh[nt][2], kh[nt][3]);
                mma16816(sd, qh[mt][0], kl2[nt][0], kl2[nt][1]);
                mma16816(sd, qh[mt][1], kl2[nt][2], kl2[nt][3]);
            }
        // V fragments (B operand for PV): tiles [8 d x 8 keys]
        uint32_t vh[2][4], vl[2][4];
        #pragma unroll
        for (int dg = 0; dg < 2; dg++){
            const int d  = dg*16 + (lg >> 1)*8 + lr;
            const int kc = (j0 >> 3) + (lg & 1);
            const uint32_t a = smb + VTH_OFF + vtaddr(d, kc);
            ldm4(vh[dg], a);
            ldm4(vl[dg], a + (VTL_OFF - VTH_OFF));
        }
        // softmax + register repack (C->A) + PV
        #pragma unroll
        for (int mt = 0; mt < 4; mt++){
            float p0[4], p1[4];
            #pragma unroll
            for (int i = 0; i < 4; i++){ p0[i] = ex2f(s[mt][0][i]); p1[i] = ex2f(s[mt][1][i]); }
            ps[mt][0] += (p0[0]+p0[1]) + (p1[0]+p1[1]);
            ps[mt][1] += (p0[2]+p0[3]) + (p1[2]+p1[3]);
            uint32_t ah[4], al[4];
            hilo2(p0[0], p0[1], ah[0], al[0]);
            hilo2(p0[2], p0[3], ah[1], al[1]);
            hilo2(p1[0], p1[1], ah[2], al[2]);
            hilo2(p1[2], p1[3], ah[3], al[3]);
            #pragma unroll
            for (int ntd = 0; ntd < 4; ntd++){
                const int dg = ntd >> 1;
                const uint32_t b0 = vh[dg][(ntd&1)*2],  b1 = vh[dg][(ntd&1)*2+1];
                const uint32_t c0 = vl[dg][(ntd&1)*2],  c1 = vl[dg][(ntd&1)*2+1];
                float* od = oAcc[mt][ntd];
                mma16816(od, ah, b0, b1);
                mma16816(od, al, b0, b1);
                mma16816(od, ah, c0, c1);
            }
        }
    }

    // ---------- row sums (4-lane bfly), normalize, stage O to smem ----------
    #pragma unroll
    for (int mt = 0; mt < 4; mt++)
        #pragma unroll
        for (int h2 = 0; h2 < 2; h2++){
            float v = ps[mt][h2];
            v += __shfl_xor_sync(0xffffffffu, v, 1);
            v += __shfl_xor_sync(0xffffffffu, v, 2);
            ps[mt][h2] = 1.f / v;
        }
    __syncthreads();   // everyone done reading K/VT smem
    #pragma unroll
    for (int mt = 0; mt < 4; mt++){
        const int r0 = qb + mt*16 + (lane >> 2);
        #pragma unroll
        for (int ntd = 0; ntd < 4; ntd++){
            const int cc = ntd*8 + 2*(lane & 3);
            float2 a, b2;
            a.x  = oAcc[mt][ntd][0] * ps[mt][0];
            a.y  = oAcc[mt][ntd][1] * ps[mt][0];
            b2.x = oAcc[mt][ntd][2] * ps[mt][1];
            b2.y = oAcc[mt][ntd][3] * ps[mt][1];
            *(float2*)(sm + OS_OFF + r0*144 + cc*4)      = a;
            *(float2*)(sm + OS_OFF + (r0+8)*144 + cc*4)  = b2;
        }
    }
    __syncthreads();

    // ---------- epilogue: LePE conv (fp32 V) + bias + store ----------
    const float* Vs  = (const float*)(sm + VF_OFF);
    const float* Wsm = (const float*)(sm + WS_OFF);
    const float* Bsm = (const float*)(sm + BS_OFF);

    #pragma unroll
    for (int rr = 0; rr < 2; rr++){
        const int n = tid + rr*256;
        float o[32];
        #pragma unroll
        for (int v = 0; v < 8; v++){
            const float4 f = *(const float4*)(sm + OS_OFF + n*144 + v*16);
            o[4*v+0] = f.x; o[4*v+1] = f.y; o[4*v+2] = f.z; o[4*v+3] = f.w;
        }
        const int rt = n >> 8, rh = (n >> 2) & 63, rws = n & 3;
        #pragma unroll
        for (int dt = -1; dt <= 1; dt++){
            const int tt = rt + dt;
            if ((unsigned)tt >= 2u) continue;
            #pragma unroll
            for (int dh = -1; dh <= 1; dh++){
                const int hh = rh + dh;
                if ((unsigned)hh >= 64u) continue;
                #pragma unroll
                for (int dw = -1; dw <= 1; dw++){
                    const int ww2 = rws + dw;
                    if ((unsigned)ww2 >= 4u) continue;
                    const int n2  = tt*256 + hh*4 + ww2;
                    const int tap = (dt+1)*9 + (dh+1)*3 + (dw+1);
                    const float* vr = Vs + n2*36;
                    const float* wr = Wsm + tap*32;
                    #pragma unroll
                    for (int i = 0; i < 32; i++) o[i] += wr[i]*vr[i];
                }
            }
        }
        const size_t l = (size_t)(lbase + rt*4096 + rh*64 + rws);
        float* op = out + batch_off + l*Cc + chan;
        #pragma unroll
        for (int v = 0; v < 8; v++){
            float4 r4;
            r4.x = o[4*v+0] + Bsm[4*v+0];
            r4.y = o[4*v+1] + Bsm[4*v+1];
            r4.z = o[4*v+2] + Bsm[4*v+2];
            r4.w = o[4*v+3] + Bsm[4*v+3];
            ((float4*)op)[v] = r4;
        }
    }
}

extern "C" void kernel_launch(void* const* d_in, const int* in_sizes, int n_in,
                              void* d_out, int out_size)
{
    const float* qkv = (const float*)d_in[0];
    const float* lw  = (const float*)d_in[1];
    const float* lb  = (const float*)d_in[2];
    float* out       = (float*)d_out;

    cudaFuncSetAttribute(lepe_hmma, cudaFuncAttributeMaxDynamicSharedMemorySize, SMEM_BYTES);
    lepe_hmma<<<512, 256, SMEM_BYTES>>>(qkv, lw, lb, out);
}

// round 6
// speedup vs baseline: 2.4993x; 1.0610x over previous
#include <cuda_runtime.h>
#include <cuda_bf16.h>
#include <cstdint>

#define Bb 2
#define Ll 32768
#define Cc 128
#define NTOK 512
#define HD 32

// ---- smem byte offsets ----
#define KH_OFF  0           // K hi: 512 rows x 64B (swizzled)     32768
#define KL_OFF  32768       // K lo                                32768
#define VTH_OFF 65536       // V^T hi: 32 d-rows x 1024B (swz)     32768
#define VTL_OFF 98304       // V^T lo                              32768
#define VF_OFF  131072      // V fp32 [512][36]                    73728
#define WS_OFF  204800      // weights [27][32] f32                 3456
#define BS_OFF  208256      // bias [32] f32                         128
#define SMEM_BYTES 208384
#define OS_OFF  0           // O fp32 [512][36] overlays K/VT after mainloop

static __device__ __forceinline__ float ex2f(float x){
    float y; asm("ex2.approx.ftz.f32 %0, %1;" : "=f"(y) : "f"(x)); return y;
}
static __device__ __forceinline__ uint32_t s2u(const void* p){
    uint32_t a;
    asm("{ .reg .u64 t; cvta.to.shared.u64 t, %1; cvt.u32.u64 %0, t; }" : "=r"(a) : "l"(p));
    return a;
}
// pack two f32 -> bf16x2 (a -> low half, b -> high half)
static __device__ __forceinline__ uint32_t pk2(float a, float b){
    uint32_t r; asm("cvt.rn.bf16x2.f32 %0, %1, %2;" : "=r"(r) : "f"(b), "f"(a)); return r;
}
// hi/lo split of a pair
static __device__ __forceinline__ void hilo2(float x, float y, uint32_t& h, uint32_t& l){
    h = pk2(x, y);
    float fx = __uint_as_float(h << 16);
    float fy = __uint_as_float(h & 0xffff0000u);
    l = pk2(x - fx, y - fy);
}
static __device__ __forceinline__ void ldm4(uint32_t* r, uint32_t a){
    asm volatile("ldmatrix.sync.aligned.m8n8.x4.shared.b16 {%0,%1,%2,%3}, [%4];"
        : "=r"(r[0]), "=r"(r[1]), "=r"(r[2]), "=r"(r[3]) : "r"(a));
}
static __device__ __forceinline__ void mma16816(float* d, const uint32_t* a, uint32_t b0, uint32_t b1){
    asm volatile("mma.sync.aligned.m16n8k16.row.col.f32.bf16.bf16.f32 "
        "{%0,%1,%2,%3},{%4,%5,%6,%7},{%8,%9},{%0,%1,%2,%3};"
        : "+f"(d[0]), "+f"(d[1]), "+f"(d[2]), "+f"(d[3])
        : "r"(a[0]), "r"(a[1]), "r"(a[2]), "r"(a[3]), "r"(b0), "r"(b1));
}
static __device__ __forceinline__ void sts_u16(uint32_t a, uint32_t v){
    asm volatile("st.shared.u16 [%0], %1;" :: "r"(a), "h"((unsigned short)v) : "memory");
}
static __device__ __forceinline__ void sts_v4(uint32_t a, uint32_t x, uint32_t y, uint32_t z, uint32_t w){
    asm volatile("st.shared.v4.b32 [%0], {%1,%2,%3,%4};" :: "r"(a), "r"(x), "r"(y), "r"(z), "r"(w) : "memory");
}
// K row addressing: 64B rows; 16B-chunk c rotated by (row>>1) so ldmatrix (8 rows, fixed c) is conflict-free
static __device__ __forceinline__ uint32_t kaddr(int n, int c){
    return (uint32_t)n*64u + ((((uint32_t)c + ((uint32_t)n >> 1)) & 3u) * 16u);
}
// V^T addressing: 1024B d-rows; low 3 bits of key-chunk XOR d
static __device__ __forceinline__ uint32_t vtaddr(int d, int kc){
    uint32_t sw = ((uint32_t)kc & ~7u) | (((uint32_t)(kc ^ d)) & 7u);
    return (uint32_t)d*1024u + sw*16u;
}

__global__ void __launch_bounds__(512, 1)
lepe_hmma(const float* __restrict__ qkv,
          const float* __restrict__ lw,
          const float* __restrict__ lb,
          float* __restrict__ out)
{
    extern __shared__ char sm[];
    const uint32_t smb = s2u(sm);
    const int tid = threadIdx.x;
    const int wid = tid >> 5, lane = tid & 31;

    const int bx = blockIdx.x;            // (window, head)
    const int win = bx >> 2, head = bx & 3;
    const int b  = win >> 6;
    const int tB = (win >> 4) & 3;
    const int wB = win & 15;
    const size_t batch_off = (size_t)b * Ll * Cc;
    const int chan  = head * HD;
    const int lbase = tB*8192 + wB*4;

    const float* qg = qkv + batch_off;
    const float* kg = qkv + (size_t)1*Bb*Ll*Cc + batch_off;
    const float* vg = qkv + (size_t)2*Bb*Ll*Cc + batch_off;

    // ---------- stage K (hi/lo), V^T (hi/lo), V fp32 ----------
    {
        const int q = tid & 3;            // 4 threads per row, 8 d-values each
        const int rbase = tid >> 2;       // 0..127
        for (int it = 0; it < 4; it++){
            const int j = it*128 + rbase;
            const int t = j >> 8, h = (j >> 2) & 63, ws = j & 3;
            const size_t l = (size_t)(lbase + t*4096 + h*64 + ws);
            const float4 k0 = *(const float4*)(kg + l*Cc + chan + q*8);
            const float4 k1 = *(const float4*)(kg + l*Cc + chan + q*8 + 4);
            uint32_t hh[4], ll[4];
            hilo2(k0.x, k0.y, hh[0], ll[0]);
            hilo2(k0.z, k0.w, hh[1], ll[1]);
            hilo2(k1.x, k1.y, hh[2], ll[2]);
            hilo2(k1.z, k1.w, hh[3], ll[3]);
            const uint32_t ka = kaddr(j, q);
            sts_v4(smb + KH_OFF + ka, hh[0], hh[1], hh[2], hh[3]);
            sts_v4(smb + KL_OFF + ka, ll[0], ll[1], ll[2], ll[3]);

            const float4 v0 = *(const float4*)(vg + l*Cc + chan + q*8);
            const float4 v1 = *(const float4*)(vg + l*Cc + chan + q*8 + 4);
            *(float4*)(sm + VF_OFF + j*144 + q*32)      = v0;
            *(float4*)(sm + VF_OFF + j*144 + q*32 + 16) = v1;
            hilo2(v0.x, v0.y, hh[0], ll[0]);
            hilo2(v0.z, v0.w, hh[1], ll[1]);
            hilo2(v1.x, v1.y, hh[2], ll[2]);
            hilo2(v1.z, v1.w, hh[3], ll[3]);
            const int kc = j >> 3;
            const uint32_t ko = (uint32_t)(j & 7) * 2u;
            #pragma unroll
            for (int e = 0; e < 8; e++){
                const int d = q*8 + e;
                const uint32_t hb  = (e & 1) ? (hh[e>>1] >> 16) : (hh[e>>1] & 0xffffu);
                const uint32_t lbv = (e & 1) ? (ll[e>>1] >> 16) : (ll[e>>1] & 0xffffu);
                const uint32_t va = vtaddr(d, kc) + ko;
                sts_u16(smb + VTH_OFF + va, hb);
                sts_u16(smb + VTL_OFF + va, lbv);
            }
        }
        for (int idx = tid; idx < 27*32; idx += 512){
            const int tap = idx >> 5, d = idx & 31;
            ((float*)(sm + WS_OFF))[tap*32 + d] = lw[(chan + d)*27 + tap];
        }
        if (tid < 32) ((float*)(sm + BS_OFF))[tid] = lb[chan + tid];
    }

    // ---------- Q fragments from gmem (scaled into log2 domain, hi/lo) ----------
    const int qb = wid * 32;              // each warp owns 32 q-rows
    uint32_t qh[2][2][4], ql[2][2][4];
    {
        const float sc = 0.17677669529663689f * 1.4426950408889634f;
        #pragma unroll
        for (int mt = 0; mt < 2; mt++){
            const int r0 = qb + mt*16 + (lane >> 2);
            const int r1 = r0 + 8;
            const int t0 = r0 >> 8, h0 = (r0 >> 2) & 63, w0 = r0 & 3;
            const int t1 = r1 >> 8, h1 = (r1 >> 2) & 63, w1 = r1 & 3;
            const float* p0 = qg + (size_t)(lbase + t0*4096 + h0*64 + w0)*Cc + chan;
            const float* p1 = qg + (size_t)(lbase + t1*4096 + h1*64 + w1)*Cc + chan;
            #pragma unroll
            for (int kt = 0; kt < 2; kt++){
                const int d0 = kt*16 + 2*(lane & 3);
                const float2 x0 = *(const float2*)(p0 + d0);
                const float2 x1 = *(const float2*)(p1 + d0);
                const float2 x2 = *(const float2*)(p0 + d0 + 8);
                const float2 x3 = *(const float2*)(p1 + d0 + 8);
                hilo2(x0.x*sc, x0.y*sc, qh[mt][kt][0], ql[mt][kt][0]);
                hilo2(x1.x*sc, x1.y*sc, qh[mt][kt][1], ql[mt][kt][1]);
                hilo2(x2.x*sc, x2.y*sc, qh[mt][kt][2], ql[mt][kt][2]);
                hilo2(x3.x*sc, x3.y*sc, qh[mt][kt][3], ql[mt][kt][3]);
            }
        }
    }
    __syncthreads();

    // ---------- mainloop: 32 subchunks of 16 keys ----------
    float oAcc[2][4][4];
    #pragma unroll
    for (int a = 0; a < 2; a++)
        #pragma unroll
        for (int b2 = 0; b2 < 4; b2++)
            #pragma unroll
            for (int c = 0; c < 4; c++) oAcc[a][b2][c] = 0.f;
    float ps[2][2] = {{0.f,0.f},{0.f,0.f}};

    const int lg = lane >> 3, lr = lane & 7;
    #pragma unroll 1
    for (int cs = 0; cs < 32; cs++){
        const int j0 = cs * 16;
        // V fragments first (independent of QK chain — LDS latency hides under MMAs)
        uint32_t vh[2][4], vl[2][4];
        #pragma unroll
        for (int dg = 0; dg < 2; dg++){
            const int d  = dg*16 + (lg >> 1)*8 + lr;
            const int kc = (j0 >> 3) + (lg & 1);
            const uint32_t a = smb + VTH_OFF + vtaddr(d, kc);
            ldm4(vh[dg], a);
            ldm4(vl[dg], a + (VTL_OFF - VTH_OFF));
        }
        // K fragments (B operand for QK): tiles [8 keys x 8 d]
        uint32_t kh[2][4], kl2[2][4];
        #pragma unroll
        for (int nt = 0; nt < 2; nt++){
            const uint32_t a = smb + KH_OFF + kaddr(j0 + nt*8 + lr, lg);
            ldm4(kh[nt], a);
            ldm4(kl2[nt], a + (KL_OFF - KH_OFF));
        }
        // S = Q K^T (3 split terms)
        float s[2][2][4];
        #pragma unroll
        for (int mt = 0; mt < 2; mt++)
            #pragma unroll
            for (int nt = 0; nt < 2; nt++){
                float* sd = s[mt][nt];
                sd[0]=sd[1]=sd[2]=sd[3]=0.f;
                mma16816(sd, qh[mt][0], kh[nt][0], kh[nt][1]);
                mma16816(sd, qh[mt][1], kh[nt][2], kh[nt][3]);
                mma16816(sd, ql[mt][0], kh[nt][0], kh[nt][1]);
                mma16816(sd, ql[mt][1], kh[nt][2], kh[nt][3]);
                mma16816(sd, qh[mt][0], kl2[nt][0], kl2[nt][1]);
                mma16816(sd, qh[mt][1], kl2[nt][2], kl2[nt][3]);
            }
        // softmax + register repack (C->A) + PV
        #pragma unroll
        for (int mt = 0; mt < 2; mt++){
            float p0[4], p1[4];
            #pragma unroll
            for (int i = 0; i < 4; i++){ p0[i] = ex2f(s[mt][0][i]); p1[i] = ex2f(s[mt][1][i]); }
            ps[mt][0] += (p0[0]+p0[1]) + (p1[0]+p1[1]);
            ps[mt][1] += (p0[2]+p0[3]) + (p1[2]+p1[3]);
            uint32_t ah[4], al[4];
            hilo2(p0[0], p0[1], ah[0], al[0]);
            hilo2(p0[2], p0[3], ah[1], al[1]);
            hilo2(p1[0], p1[1], ah[2], al[2]);
            hilo2(p1[2], p1[3], ah[3], al[3]);
            #pragma unroll
            for (int ntd = 0; ntd < 4; ntd++){
                const int dg = ntd >> 1;
                const uint32_t b0 = vh[dg][(ntd&1)*2],  b1 = vh[dg][(ntd&1)*2+1];
                const uint32_t c0 = vl[dg][(ntd&1)*2],  c1 = vl[dg][(ntd&1)*2+1];
                float* od = oAcc[mt][ntd];
                mma16816(od, ah, b0, b1);
                mma16816(od, al, b0, b1);
                mma16816(od, ah, c0, c1);
            }
        }
    }

    // ---------- row sums (4-lane bfly), normalize, stage O to smem ----------
    #pragma unroll
    for (int mt = 0; mt < 2; mt++)
        #pragma unroll
        for (int h2 = 0; h2 < 2; h2++){
            float v = ps[mt][h2];
            v += __shfl_xor_sync(0xffffffffu, v, 1);
            v += __shfl_xor_sync(0xffffffffu, v, 2);
            ps[mt][h2] = 1.f / v;
        }
    __syncthreads();   // everyone done reading K/VT smem
    #pragma unroll
    for (int mt = 0; mt < 2; mt++){
        const int r0 = qb + mt*16 + (lane >> 2);
        #pragma unroll
        for (int ntd = 0; ntd < 4; ntd++){
            const int cc = ntd*8 + 2*(lane & 3);
            float2 a, b2;
            a.x  = oAcc[mt][ntd][0] * ps[mt][0];
            a.y  = oAcc[mt][ntd][1] * ps[mt][0];
            b2.x = oAcc[mt][ntd][2] * ps[mt][1];
            b2.y = oAcc[mt][ntd][3] * ps[mt][1];
            *(float2*)(sm + OS_OFF + r0*144 + cc*4)      = a;
            *(float2*)(sm + OS_OFF + (r0+8)*144 + cc*4)  = b2;
        }
    }
    __syncthreads();

    // ---------- epilogue: LePE conv (fp32 V) + bias + store ----------
    const float* Vs  = (const float*)(sm + VF_OFF);
    const float* Wsm = (const float*)(sm + WS_OFF);
    const float* Bsm = (const float*)(sm + BS_OFF);

    {
        const int n = tid;                 // one row per thread
        float o[32];
        #pragma unroll
        for (int v = 0; v < 8; v++){
            const float4 f = *(const float4*)(sm + OS_OFF + n*144 + v*16);
            o[4*v+0] = f.x; o[4*v+1] = f.y; o[4*v+2] = f.z; o[4*v+3] = f.w;
        }
        const int rt = n >> 8, rh = (n >> 2) & 63, rws = n & 3;
        #pragma unroll
        for (int dt = -1; dt <= 1; dt++){
            const int tt = rt + dt;
            if ((unsigned)tt >= 2u) continue;
            #pragma unroll
            for (int dh = -1; dh <= 1; dh++){
                const int hh = rh + dh;
                if ((unsigned)hh >= 64u) continue;
                #pragma unroll
                for (int dw = -1; dw <= 1; dw++){
                    const int ww2 = rws + dw;
                    if ((unsigned)ww2 >= 4u) continue;
                    const int n2  = tt*256 + hh*4 + ww2;
                    const int tap = (dt+1)*9 + (dh+1)*3 + (dw+1);
                    const float* vr = Vs + n2*36;
                    const float* wr = Wsm + tap*32;
                    #pragma unroll
                    for (int i = 0; i < 32; i++) o[i] += wr[i]*vr[i];
                }
            }
        }
        const size_t l = (size_t)(lbase + rt*4096 + rh*64 + rws);
        float* op = out + batch_off + l*Cc + chan;
        #pragma unroll
        for (int v = 0; v < 8; v++){
            float4 r4;
            r4.x = o[4*v+0] + Bsm[4*v+0];
            r4.y = o[4*v+1] + Bsm[4*v+1];
            r4.z = o[4*v+2] + Bsm[4*v+2];
            r4.w = o[4*v+3] + Bsm[4*v+3];
            ((float4*)op)[v] = r4;
        }
    }
}

extern "C" void kernel_launch(void* const* d_in, const int* in_sizes, int n_in,
                              void* d_out, int out_size)
{
    const float* qkv = (const float*)d_in[0];
    const float* lw  = (const float*)d_in[1];
    const float* lb  = (const float*)d_in[2];
    float* out       = (float*)d_out;

    cudaFuncSetAttribute(lepe_hmma, cudaFuncAttributeMaxDynamicSharedMemorySize, SMEM_BYTES);
    lepe_hmma<<<512, 512, SMEM_BYTES>>>(qkv, lw, lb, out);
}